// round 10
// baseline (speedup 1.0000x reference)
#include <cuda_runtime.h>
#include <math.h>
#include <stdint.h>

#define T_ 2048
#define D_ 1024
#define I_ 2048
#define E_ 8

// ---------------- device scratch ----------------
__device__ int   g_cnt[E_];
__device__ int   g_off[E_];
__device__ int   g_tok[E_ * T_];
__device__ float g_scr[E_ * T_];
__device__ float g_h[(size_t)2 * T_ * I_];        // 4096 x 2048 fp32 (tf32-rounded)
__device__ float x_r[(size_t)T_ * D_];            // tf32-rounded x

// ---------------- helpers ----------------
__device__ __forceinline__ unsigned f2tf(float f) {
    unsigned u; asm("cvt.rna.tf32.f32 %0, %1;" : "=r"(u) : "f"(f)); return u;
}
__device__ __forceinline__ float4 cvt4(float4 v) {
    float4 r;
    r.x = __uint_as_float(f2tf(v.x));
    r.y = __uint_as_float(f2tf(v.y));
    r.z = __uint_as_float(f2tf(v.z));
    r.w = __uint_as_float(f2tf(v.w));
    return r;
}
__device__ __forceinline__ void mma_tf32(float* c, const unsigned* a, const unsigned* b) {
    asm volatile("mma.sync.aligned.m16n8k8.row.col.f32.tf32.tf32.f32 "
                 "{%0,%1,%2,%3}, {%4,%5,%6,%7}, {%8,%9}, {%0,%1,%2,%3};"
                 : "+f"(c[0]), "+f"(c[1]), "+f"(c[2]), "+f"(c[3])
                 : "r"(a[0]), "r"(a[1]), "r"(a[2]), "r"(a[3]), "r"(b[0]), "r"(b[1]));
}
__device__ __forceinline__ void cp16(unsigned dst, const void* src) {
    asm volatile("cp.async.cg.shared.global [%0], [%1], 16;" :: "r"(dst), "l"(src));
}
__device__ __forceinline__ void cp_commit() { asm volatile("cp.async.commit_group;"); }
__device__ __forceinline__ void cp_wait2()  { asm volatile("cp.async.wait_group 2;"); }

// interleave two cvt'd float4 (rows k and k+4) into pair layout, 32B contiguous
__device__ __forceinline__ void stb(float* dst, float4 v0, float4 v1) {
    *(float4*)(dst)     = make_float4(v0.x, v1.x, v0.y, v1.y);
    *(float4*)(dst + 4) = make_float4(v0.z, v1.z, v0.w, v1.w);
}

// 4-stage pipeline smem: A planes then B planes, 8KB each per stage
#define STG 4
#define A_STAGE_F 2048            // floats per A stage (128x16)
#define B_STAGE_F 2048            // floats per B stage (8 pair-rows x 128 float2)
#define SMEM_TOT (STG * (A_STAGE_F + B_STAGE_F) * 4)   // 65536 bytes

// ---------------- init: zero routing counters ----------------
__global__ void k_init() {
    if (threadIdx.x < E_) g_cnt[threadIdx.x] = 0;
}

// ---------------- fused gate: logits + top2 + x_r write + out zero ----------------
__global__ void k_gate(const float* __restrict__ x, const float* __restrict__ gw,
                       float* __restrict__ out) {
    const int t    = blockIdx.x * 8 + (threadIdx.x >> 5);
    const int lane = threadIdx.x & 31;
    const float* xr = x + (size_t)t * D_;
    float*       xo = x_r + (size_t)t * D_;
    float*       oo = out + (size_t)t * D_;
    const float4 z4 = make_float4(0.f, 0.f, 0.f, 0.f);

    float p[E_];
#pragma unroll
    for (int e = 0; e < E_; e++) p[e] = 0.f;

    for (int d = lane * 4; d < D_; d += 128) {
        float4 xv = *(const float4*)(xr + d);
        *(float4*)(xo + d) = cvt4(xv);
        *(float4*)(oo + d) = z4;
#pragma unroll
        for (int e = 0; e < E_; e++) {
            float4 gv = *(const float4*)(gw + e * D_ + d);
            p[e] += xv.x * gv.x + xv.y * gv.y + xv.z * gv.z + xv.w * gv.w;
        }
    }
#pragma unroll
    for (int o = 16; o; o >>= 1) {
#pragma unroll
        for (int e = 0; e < E_; e++) p[e] += __shfl_down_sync(0xffffffffu, p[e], o);
    }

    if (lane == 0) {
        float mx = p[0];
#pragma unroll
        for (int e = 1; e < E_; e++) mx = fmaxf(mx, p[e]);
        float pr[E_]; float den = 0.f;
#pragma unroll
        for (int e = 0; e < E_; e++) { pr[e] = expf(p[e] - mx); den += pr[e]; }
        float inv = 1.f / den;
#pragma unroll
        for (int e = 0; e < E_; e++) pr[e] *= inv;

        int e1 = 0;
#pragma unroll
        for (int e = 1; e < E_; e++) if (pr[e] > pr[e1]) e1 = e;
        int e2 = (e1 == 0) ? 1 : 0;
#pragma unroll
        for (int e = 0; e < E_; e++) if (e != e1 && pr[e] > pr[e2]) e2 = e;

        int i1 = atomicAdd(&g_cnt[e1], 1);
        g_tok[e1 * T_ + i1] = t; g_scr[e1 * T_ + i1] = pr[e1];
        int i2 = atomicAdd(&g_cnt[e2], 1);
        g_tok[e2 * T_ + i2] = t; g_scr[e2 * T_ + i2] = pr[e2];
    }
}

__global__ void k_prefix() {
    if (threadIdx.x == 0) {
        int s = 0;
#pragma unroll
        for (int e = 0; e < E_; e++) { g_off[e] = s; s += g_cnt[e]; }
    }
}

// Layouts:
//   A smem [128][16] swizzled: kswz = (k + 4*((m>>1)&3)) & 15  (unchanged)
//   B smem paired: pair-row kp in 0..7 holds float2(B[ka][n], B[ka+4][n]),
//     ka = (kp&3) + 8*(kp>>2), stored at float2 index kp*128 + (n ^ (4*(kp&3)))

// ---------------- GEMM1: h = silu(gather(x_r) @ tf32(w1[e])) ----------------
__global__ __launch_bounds__(256, 2) void k_ffn1(const float* __restrict__ w1) {
    const int e    = blockIdx.z;
    const int cnt  = g_cnt[e];
    const int row0 = blockIdx.y * 128;
    if (row0 >= cnt) return;
    const int n0b = blockIdx.x * 128;
    const int off = g_off[e];
    const float* Bw = w1 + (size_t)e * D_ * I_;

    extern __shared__ float dsm[];
    float* Abase = dsm;                          // 4 stages x 2048 f
    float* Bbase = dsm + STG * A_STAGE_F;        // 4 stages x 2048 f

    const int tid = threadIdx.x;

    const int rA  = tid >> 2;            // 0..63
    const int kcA = (tid & 3) * 4;
    const int gr0 = min(row0 + rA,      cnt - 1);
    const int gr1 = min(row0 + rA + 64, cnt - 1);
    const float* aS0 = x_r + (size_t)g_tok[e * T_ + gr0] * D_ + kcA;
    const float* aS1 = x_r + (size_t)g_tok[e * T_ + gr1] * D_ + kcA;
    const int rA1 = rA + 64;
    const unsigned aD0 = (unsigned)__cvta_generic_to_shared(
        &Abase[rA  * 16 + ((kcA + 4 * ((rA  >> 1) & 3)) & 15)]);
    const unsigned aD1 = (unsigned)__cvta_generic_to_shared(
        &Abase[rA1 * 16 + ((kcA + 4 * ((rA1 >> 1) & 3)) & 15)]);

    // B staging: pair-row kp, rows ka and ka+4
    const int kp  = tid >> 5;            // 0..7
    const int ncB = (tid & 31) * 4;
    const int ka  = (kp & 3) + ((kp >> 2) << 3);
    const float* bS0 = Bw + (size_t)ka * I_ + n0b + ncB;
    const float* bS1 = Bw + (size_t)(ka + 4) * I_ + n0b + ncB;
    float* bP = &Bbase[kp * 256 + ((ncB ^ (4 * (kp & 3))) << 1)];

    const int wid = tid >> 5, lane = tid & 31;
    const int wm = wid & 3, wn = wid >> 2;
    const int qr = lane >> 2, qc = lane & 3;

    float c[2][8][4];
#pragma unroll
    for (int i = 0; i < 2; i++)
#pragma unroll
        for (int j = 0; j < 8; j++)
#pragma unroll
            for (int l = 0; l < 4; l++) c[i][j][l] = 0.f;

    const int KT = D_ / 16;   // 64
#pragma unroll
    for (int p = 0; p < 3; p++) {
        const unsigned so = p * (A_STAGE_F * 4);
        const int k0 = p * 16;
        cp16(aD0 + so, aS0 + k0);
        cp16(aD1 + so, aS1 + k0);
        cp_commit();
        stb(bP + p * B_STAGE_F,
            cvt4(*(const float4*)(bS0 + (size_t)k0 * I_)),
            cvt4(*(const float4*)(bS1 + (size_t)k0 * I_)));
    }
    float4 nb0 = *(const float4*)(bS0 + (size_t)48 * I_);
    float4 nb1 = *(const float4*)(bS1 + (size_t)48 * I_);
    __syncthreads();

    for (int kt = 0; kt < KT; kt++) {
        cp_wait2();
        __syncthreads();
        if (kt + 3 < KT) {
            const int s = (kt + 3) & 3;
            const int k0 = (kt + 3) * 16;
            cp16(aD0 + s * (A_STAGE_F * 4), aS0 + k0);
            cp16(aD1 + s * (A_STAGE_F * 4), aS1 + k0);
            stb(bP + s * B_STAGE_F, cvt4(nb0), cvt4(nb1));
        }
        cp_commit();
        if (kt + 4 < KT) {
            const int k0 = (kt + 4) * 16;
            nb0 = *(const float4*)(bS0 + (size_t)k0 * I_);
            nb1 = *(const float4*)(bS1 + (size_t)k0 * I_);
        }
        const float* Ab = Abase + (kt & 3) * A_STAGE_F;
        const float* Bb = Bbase + (kt & 3) * B_STAGE_F;
#pragma unroll
        for (int ks = 0; ks < 2; ks++) {
            const int kb = ks * 8 + qc;
            const int kprow = (ks * 4 + qc) * 256;     // float index of pair-row base
            unsigned af[2][4];
#pragma unroll
            for (int mt = 0; mt < 2; mt++) {
                const int mlo = wm * 32 + mt * 16 + qr;
                const int mhi = mlo + 8;
                af[mt][0] = __float_as_uint(Ab[mlo * 16 + ((kb     + 4 * ((mlo >> 1) & 3)) & 15)]);
                af[mt][1] = __float_as_uint(Ab[mhi * 16 + ((kb     + 4 * ((mhi >> 1) & 3)) & 15)]);
                af[mt][2] = __float_as_uint(Ab[mlo * 16 + ((kb + 4 + 4 * ((mlo >> 1) & 3)) & 15)]);
                af[mt][3] = __float_as_uint(Ab[mhi * 16 + ((kb + 4 + 4 * ((mhi >> 1) & 3)) & 15)]);
            }
#pragma unroll
            for (int nt = 0; nt < 8; nt++) {
                const int n = wn * 64 + nt * 8 + qr;
                float2 bp = *(const float2*)&Bb[kprow + ((n ^ (4 * qc)) << 1)];
                unsigned bf[2];
                bf[0] = __float_as_uint(bp.x);
                bf[1] = __float_as_uint(bp.y);
                mma_tf32(c[0][nt], af[0], bf);
                mma_tf32(c[1][nt], af[1], bf);
            }
        }
    }

    // epilogue: silu -> g_h (stored tf32-rounded, so ffn2 needs no CVT for A)
#pragma unroll
    for (int mt = 0; mt < 2; mt++) {
        const int r = row0 + wm * 32 + mt * 16 + qr;
#pragma unroll
        for (int nt = 0; nt < 8; nt++) {
            const int n = n0b + wn * 64 + nt * 8 + 2 * qc;
            if (r < cnt) {
                float* p = g_h + (size_t)(off + r) * I_ + n;
                float v0 = c[mt][nt][0], v1 = c[mt][nt][1];
                p[0] = __uint_as_float(f2tf(v0 / (1.f + expf(-v0))));
                p[1] = __uint_as_float(f2tf(v1 / (1.f + expf(-v1))));
            }
            if (r + 8 < cnt) {
                float* p = g_h + (size_t)(off + r + 8) * I_ + n;
                float v2 = c[mt][nt][2], v3 = c[mt][nt][3];
                p[0] = __uint_as_float(f2tf(v2 / (1.f + expf(-v2))));
                p[1] = __uint_as_float(f2tf(v3 / (1.f + expf(-v3))));
            }
        }
    }
}

// ---------------- GEMM2: out[tok] += score * (g_h @ tf32(w2[e])) ----------------
__global__ __launch_bounds__(256, 2) void k_ffn2(const float* __restrict__ w2,
                                                 float* __restrict__ out) {
    const int e    = blockIdx.z;
    const int cnt  = g_cnt[e];
    const int row0 = blockIdx.y * 128;
    if (row0 >= cnt) return;
    const int n0b = blockIdx.x * 128;
    const int off = g_off[e];
    const float* Bw = w2 + (size_t)e * I_ * D_;

    extern __shared__ float dsm[];
    float* Abase = dsm;
    float* Bbase = dsm + STG * A_STAGE_F;

    const int tid = threadIdx.x;

    const int rA  = tid >> 2;
    const int kcA = (tid & 3) * 4;
    const int gr0 = min(row0 + rA,      cnt - 1);
    const int gr1 = min(row0 + rA + 64, cnt - 1);
    const float* aS0 = g_h + (size_t)(off + gr0) * I_ + kcA;
    const float* aS1 = g_h + (size_t)(off + gr1) * I_ + kcA;
    const int rA1 = rA + 64;
    const unsigned aD0 = (unsigned)__cvta_generic_to_shared(
        &Abase[rA  * 16 + ((kcA + 4 * ((rA  >> 1) & 3)) & 15)]);
    const unsigned aD1 = (unsigned)__cvta_generic_to_shared(
        &Abase[rA1 * 16 + ((kcA + 4 * ((rA1 >> 1) & 3)) & 15)]);

    const int kp  = tid >> 5;
    const int ncB = (tid & 31) * 4;
    const int ka  = (kp & 3) + ((kp >> 2) << 3);
    const float* bS0 = Bw + (size_t)ka * D_ + n0b + ncB;
    const float* bS1 = Bw + (size_t)(ka + 4) * D_ + n0b + ncB;
    float* bP = &Bbase[kp * 256 + ((ncB ^ (4 * (kp & 3))) << 1)];

    const int wid = tid >> 5, lane = tid & 31;
    const int wm = wid & 3, wn = wid >> 2;
    const int qr = lane >> 2, qc = lane & 3;

    float c[2][8][4];
#pragma unroll
    for (int i = 0; i < 2; i++)
#pragma unroll
        for (int j = 0; j < 8; j++)
#pragma unroll
            for (int l = 0; l < 4; l++) c[i][j][l] = 0.f;

    const int KT = I_ / 16;   // 128
#pragma unroll
    for (int p = 0; p < 3; p++) {
        const unsigned so = p * (A_STAGE_F * 4);
        const int k0 = p * 16;
        cp16(aD0 + so, aS0 + k0);
        cp16(aD1 + so, aS1 + k0);
        cp_commit();
        stb(bP + p * B_STAGE_F,
            cvt4(*(const float4*)(bS0 + (size_t)k0 * D_)),
            cvt4(*(const float4*)(bS1 + (size_t)k0 * D_)));
    }
    float4 nb0 = *(const float4*)(bS0 + (size_t)48 * D_);
    float4 nb1 = *(const float4*)(bS1 + (size_t)48 * D_);
    __syncthreads();

    for (int kt = 0; kt < KT; kt++) {
        cp_wait2();
        __syncthreads();
        if (kt + 3 < KT) {
            const int s = (kt + 3) & 3;
            const int k0 = (kt + 3) * 16;
            cp16(aD0 + s * (A_STAGE_F * 4), aS0 + k0);
            cp16(aD1 + s * (A_STAGE_F * 4), aS1 + k0);
            stb(bP + s * B_STAGE_F, cvt4(nb0), cvt4(nb1));
        }
        cp_commit();
        if (kt + 4 < KT) {
            const int k0 = (kt + 4) * 16;
            nb0 = *(const float4*)(bS0 + (size_t)k0 * D_);
            nb1 = *(const float4*)(bS1 + (size_t)k0 * D_);
        }
        const float* Ab = Abase + (kt & 3) * A_STAGE_F;
        const float* Bb = Bbase + (kt & 3) * B_STAGE_F;
#pragma unroll
        for (int ks = 0; ks < 2; ks++) {
            const int kb = ks * 8 + qc;
            const int kprow = (ks * 4 + qc) * 256;
            unsigned af[2][4];
#pragma unroll
            for (int mt = 0; mt < 2; mt++) {
                const int mlo = wm * 32 + mt * 16 + qr;
                const int mhi = mlo + 8;
                af[mt][0] = __float_as_uint(Ab[mlo * 16 + ((kb     + 4 * ((mlo >> 1) & 3)) & 15)]);
                af[mt][1] = __float_as_uint(Ab[mhi * 16 + ((kb     + 4 * ((mhi >> 1) & 3)) & 15)]);
                af[mt][2] = __float_as_uint(Ab[mlo * 16 + ((kb + 4 + 4 * ((mlo >> 1) & 3)) & 15)]);
                af[mt][3] = __float_as_uint(Ab[mhi * 16 + ((kb + 4 + 4 * ((mhi >> 1) & 3)) & 15)]);
            }
#pragma unroll
            for (int nt = 0; nt < 8; nt++) {
                const int n = wn * 64 + nt * 8 + qr;
                float2 bp = *(const float2*)&Bb[kprow + ((n ^ (4 * qc)) << 1)];
                unsigned bf[2];
                bf[0] = __float_as_uint(bp.x);
                bf[1] = __float_as_uint(bp.y);
                mma_tf32(c[0][nt], af[0], bf);
                mma_tf32(c[1][nt], af[1], bf);
            }
        }
    }

    // epilogue: scaled atomic scatter
#pragma unroll
    for (int mt = 0; mt < 2; mt++) {
        const int r = row0 + wm * 32 + mt * 16 + qr;
        int   tok0 = 0, tok1 = 0; float s0 = 0.f, s1 = 0.f;
        const bool v0 = (r < cnt), v1 = (r + 8 < cnt);
        if (v0) { tok0 = g_tok[e * T_ + r];     s0 = g_scr[e * T_ + r]; }
        if (v1) { tok1 = g_tok[e * T_ + r + 8]; s1 = g_scr[e * T_ + r + 8]; }
#pragma unroll
        for (int nt = 0; nt < 8; nt++) {
            const int n = n0b + wn * 64 + nt * 8 + 2 * qc;
            if (v0) {
                float* p = out + (size_t)tok0 * D_ + n;
                atomicAdd(p,     s0 * c[mt][nt][0]);
                atomicAdd(p + 1, s0 * c[mt][nt][1]);
            }
            if (v1) {
                float* p = out + (size_t)tok1 * D_ + n;
                atomicAdd(p,     s1 * c[mt][nt][2]);
                atomicAdd(p + 1, s1 * c[mt][nt][3]);
            }
        }
    }
}

// ---------------- launch ----------------
extern "C" void kernel_launch(void* const* d_in, const int* in_sizes, int n_in,
                              void* d_out, int out_size) {
    const float* x  = (const float*)d_in[0];
    const float* gw = (const float*)d_in[1];
    const float* w1 = (const float*)d_in[2];
    const float* w2 = (const float*)d_in[3];
    float* out = (float*)d_out;

    static bool attr_set = false;
    if (!attr_set) {
        cudaFuncSetAttribute(k_ffn1, cudaFuncAttributeMaxDynamicSharedMemorySize, SMEM_TOT);
        cudaFuncSetAttribute(k_ffn2, cudaFuncAttributeMaxDynamicSharedMemorySize, SMEM_TOT);
        attr_set = true;
    }

    k_init<<<1, 32>>>();
    k_gate<<<T_ / 8, 256>>>(x, gw, out);
    k_prefix<<<1, 32>>>();
    k_ffn1<<<dim3(I_ / 128, T_ / 128, E_), 256, SMEM_TOT>>>(w1);
    k_ffn2<<<dim3(D_ / 128, T_ / 128, E_), 256, SMEM_TOT>>>(w2, out);
}

// round 11
// speedup vs baseline: 1.1224x; 1.1224x over previous
#include <cuda_runtime.h>
#include <math.h>
#include <stdint.h>

#define T_ 2048
#define D_ 1024
#define I_ 2048
#define E_ 8

// ---------------- device scratch ----------------
__device__ int   g_cnt[E_];
__device__ int   g_off[E_];
__device__ int   g_tok[E_ * T_];
__device__ float g_scr[E_ * T_];
__device__ float g_h[(size_t)2 * T_ * I_];        // 4096 x 2048 fp32 (tf32-rounded)
__device__ float x_r[(size_t)T_ * D_];            // tf32-rounded x

// ---------------- helpers ----------------
__device__ __forceinline__ unsigned f2tf(float f) {
    unsigned u; asm("cvt.rna.tf32.f32 %0, %1;" : "=r"(u) : "f"(f)); return u;
}
__device__ __forceinline__ float4 cvt4(float4 v) {
    float4 r;
    r.x = __uint_as_float(f2tf(v.x));
    r.y = __uint_as_float(f2tf(v.y));
    r.z = __uint_as_float(f2tf(v.z));
    r.w = __uint_as_float(f2tf(v.w));
    return r;
}
__device__ __forceinline__ void mma_tf32(float* c, const unsigned* a, const unsigned* b) {
    asm volatile("mma.sync.aligned.m16n8k8.row.col.f32.tf32.tf32.f32 "
                 "{%0,%1,%2,%3}, {%4,%5,%6,%7}, {%8,%9}, {%0,%1,%2,%3};"
                 : "+f"(c[0]), "+f"(c[1]), "+f"(c[2]), "+f"(c[3])
                 : "r"(a[0]), "r"(a[1]), "r"(a[2]), "r"(a[3]), "r"(b[0]), "r"(b[1]));
}
__device__ __forceinline__ void cp16(unsigned dst, const void* src) {
    asm volatile("cp.async.cg.shared.global [%0], [%1], 16;" :: "r"(dst), "l"(src));
}
__device__ __forceinline__ void cp_commit() { asm volatile("cp.async.commit_group;"); }
__device__ __forceinline__ void cp_wait2()  { asm volatile("cp.async.wait_group 2;"); }

// 6-stage pipeline smem: A planes then B planes, 8KB each per stage
#define STG 6
#define A_STAGE_F 2048            // floats per A stage (128x16)
#define B_STAGE_F 2048            // floats per B stage (16x128)
#define SMEM_TOT (STG * (A_STAGE_F + B_STAGE_F) * 4)   // 98304 bytes

// ---------------- init: zero routing counters ----------------
__global__ void k_init() {
    if (threadIdx.x < E_) g_cnt[threadIdx.x] = 0;
}

// ---------------- fused gate: logits + top2 + x_r write + out zero ----------------
__global__ void k_gate(const float* __restrict__ x, const float* __restrict__ gw,
                       float* __restrict__ out) {
    const int t    = blockIdx.x * 8 + (threadIdx.x >> 5);
    const int lane = threadIdx.x & 31;
    const float* xr = x + (size_t)t * D_;
    float*       xo = x_r + (size_t)t * D_;
    float*       oo = out + (size_t)t * D_;
    const float4 z4 = make_float4(0.f, 0.f, 0.f, 0.f);

    float p[E_];
#pragma unroll
    for (int e = 0; e < E_; e++) p[e] = 0.f;

    for (int d = lane * 4; d < D_; d += 128) {
        float4 xv = *(const float4*)(xr + d);
        *(float4*)(xo + d) = cvt4(xv);
        *(float4*)(oo + d) = z4;
#pragma unroll
        for (int e = 0; e < E_; e++) {
            float4 gv = *(const float4*)(gw + e * D_ + d);
            p[e] += xv.x * gv.x + xv.y * gv.y + xv.z * gv.z + xv.w * gv.w;
        }
    }
#pragma unroll
    for (int o = 16; o; o >>= 1) {
#pragma unroll
        for (int e = 0; e < E_; e++) p[e] += __shfl_down_sync(0xffffffffu, p[e], o);
    }

    if (lane == 0) {
        float mx = p[0];
#pragma unroll
        for (int e = 1; e < E_; e++) mx = fmaxf(mx, p[e]);
        float pr[E_]; float den = 0.f;
#pragma unroll
        for (int e = 0; e < E_; e++) { pr[e] = expf(p[e] - mx); den += pr[e]; }
        float inv = 1.f / den;
#pragma unroll
        for (int e = 0; e < E_; e++) pr[e] *= inv;

        int e1 = 0;
#pragma unroll
        for (int e = 1; e < E_; e++) if (pr[e] > pr[e1]) e1 = e;
        int e2 = (e1 == 0) ? 1 : 0;
#pragma unroll
        for (int e = 0; e < E_; e++) if (e != e1 && pr[e] > pr[e2]) e2 = e;

        int i1 = atomicAdd(&g_cnt[e1], 1);
        g_tok[e1 * T_ + i1] = t; g_scr[e1 * T_ + i1] = pr[e1];
        int i2 = atomicAdd(&g_cnt[e2], 1);
        g_tok[e2 * T_ + i2] = t; g_scr[e2 * T_ + i2] = pr[e2];
    }
}

__global__ void k_prefix() {
    if (threadIdx.x == 0) {
        int s = 0;
#pragma unroll
        for (int e = 0; e < E_; e++) { g_off[e] = s; s += g_cnt[e]; }
    }
}

// Swizzles (conflict-free for tf32 m16n8k8 fragment reads):
//   A smem [128][16]: kswz = (k + 4*((m>>1)&3)) & 15
//   B smem [16][128]: nswz = n ^ (8*(k&3))

// ---------------- GEMM1: h = silu(gather(x_r) @ tf32(w1[e])) ----------------
__global__ __launch_bounds__(256, 2) void k_ffn1(const float* __restrict__ w1) {
    const int e    = blockIdx.z;
    const int cnt  = g_cnt[e];
    const int row0 = blockIdx.y * 128;
    if (row0 >= cnt) return;
    const int n0b = blockIdx.x * 128;
    const int off = g_off[e];
    const float* Bw = w1 + (size_t)e * D_ * I_;

    extern __shared__ float dsm[];
    float* Abase = dsm;                          // 6 stages x 2048 f
    float* Bbase = dsm + STG * A_STAGE_F;        // 6 stages x 2048 f

    const int tid = threadIdx.x;

    const int rA  = tid >> 2;            // 0..63
    const int kcA = (tid & 3) * 4;
    const int gr0 = min(row0 + rA,      cnt - 1);
    const int gr1 = min(row0 + rA + 64, cnt - 1);
    const float* aS0 = x_r + (size_t)g_tok[e * T_ + gr0] * D_ + kcA;
    const float* aS1 = x_r + (size_t)g_tok[e * T_ + gr1] * D_ + kcA;
    const int rA1 = rA + 64;
    const unsigned aD0 = (unsigned)__cvta_generic_to_shared(
        &Abase[rA  * 16 + ((kcA + 4 * ((rA  >> 1) & 3)) & 15)]);
    const unsigned aD1 = (unsigned)__cvta_generic_to_shared(
        &Abase[rA1 * 16 + ((kcA + 4 * ((rA1 >> 1) & 3)) & 15)]);

    const int rB  = tid >> 5;            // 0..7
    const int ncB = (tid & 31) * 4;
    const float* bS0 = Bw + (size_t)rB * I_ + n0b + ncB;
    const float* bS1 = bS0 + (size_t)8 * I_;
    float* bP0 = &Bbase[rB * 128 + (ncB ^ (8 * (rB & 3)))];
    float* bP1 = &Bbase[(rB + 8) * 128 + (ncB ^ (8 * (rB & 3)))];

    const int wid = tid >> 5, lane = tid & 31;
    const int wm = wid & 3, wn = wid >> 2;
    const int qr = lane >> 2, qc = lane & 3;

    float c[2][8][4];
#pragma unroll
    for (int i = 0; i < 2; i++)
#pragma unroll
        for (int j = 0; j < 8; j++)
#pragma unroll
            for (int l = 0; l < 4; l++) c[i][j][l] = 0.f;

    const int KT = D_ / 16;   // 64
    // prologue: A tiles 0..3 via cp.async (one commit each); B tiles 0..3 direct
#pragma unroll
    for (int p = 0; p < 4; p++) {
        const unsigned so = p * (A_STAGE_F * 4);
        const int k0 = p * 16;
        cp16(aD0 + so, aS0 + k0);
        cp16(aD1 + so, aS1 + k0);
        cp_commit();
        *(float4*)(bP0 + p * B_STAGE_F) = cvt4(*(const float4*)(bS0 + (size_t)k0 * I_));
        *(float4*)(bP1 + p * B_STAGE_F) = cvt4(*(const float4*)(bS1 + (size_t)k0 * I_));
    }
    float4 nb0 = *(const float4*)(bS0 + (size_t)64 * I_);   // B tile 4
    float4 nb1 = *(const float4*)(bS1 + (size_t)64 * I_);

    int scur = 0, spre = 4;
    for (int kt = 0; kt < KT; kt++) {
        if (!(kt & 1)) { cp_wait2(); __syncthreads(); }
        if (kt + 4 < KT) {
            const unsigned so = spre * (A_STAGE_F * 4);
            const int k0 = (kt + 4) * 16;
            cp16(aD0 + so, aS0 + k0);
            cp16(aD1 + so, aS1 + k0);
            *(float4*)(bP0 + spre * B_STAGE_F) = cvt4(nb0);
            *(float4*)(bP1 + spre * B_STAGE_F) = cvt4(nb1);
        }
        cp_commit();
        if (kt + 5 < KT) {
            const int k0 = (kt + 5) * 16;
            nb0 = *(const float4*)(bS0 + (size_t)k0 * I_);
            nb1 = *(const float4*)(bS1 + (size_t)k0 * I_);
        }
        const float* Ab = Abase + scur * A_STAGE_F;
        const float* Bb = Bbase + scur * B_STAGE_F;
#pragma unroll
        for (int ks = 0; ks < 2; ks++) {
            const int kb = ks * 8 + qc;
            unsigned af[2][4];
#pragma unroll
            for (int mt = 0; mt < 2; mt++) {
                const int mlo = wm * 32 + mt * 16 + qr;
                const int mhi = mlo + 8;
                af[mt][0] = __float_as_uint(Ab[mlo * 16 + ((kb     + 4 * ((mlo >> 1) & 3)) & 15)]);
                af[mt][1] = __float_as_uint(Ab[mhi * 16 + ((kb     + 4 * ((mhi >> 1) & 3)) & 15)]);
                af[mt][2] = __float_as_uint(Ab[mlo * 16 + ((kb + 4 + 4 * ((mlo >> 1) & 3)) & 15)]);
                af[mt][3] = __float_as_uint(Ab[mhi * 16 + ((kb + 4 + 4 * ((mhi >> 1) & 3)) & 15)]);
            }
#pragma unroll
            for (int nt = 0; nt < 8; nt++) {
                const int n = wn * 64 + nt * 8 + qr;
                const unsigned sw = n ^ (8 * (kb & 3));
                unsigned bf[2];
                bf[0] = __float_as_uint(Bb[kb * 128 + sw]);
                bf[1] = __float_as_uint(Bb[(kb + 4) * 128 + sw]);
                mma_tf32(c[0][nt], af[0], bf);
                mma_tf32(c[1][nt], af[1], bf);
            }
        }
        if (++scur == STG) scur = 0;
        if (++spre == STG) spre = 0;
    }

    // epilogue: silu -> g_h (stored tf32-rounded, so ffn2 needs no CVT for A)
#pragma unroll
    for (int mt = 0; mt < 2; mt++) {
        const int r = row0 + wm * 32 + mt * 16 + qr;
#pragma unroll
        for (int nt = 0; nt < 8; nt++) {
            const int n = n0b + wn * 64 + nt * 8 + 2 * qc;
            if (r < cnt) {
                float* p = g_h + (size_t)(off + r) * I_ + n;
                float v0 = c[mt][nt][0], v1 = c[mt][nt][1];
                p[0] = __uint_as_float(f2tf(v0 / (1.f + expf(-v0))));
                p[1] = __uint_as_float(f2tf(v1 / (1.f + expf(-v1))));
            }
            if (r + 8 < cnt) {
                float* p = g_h + (size_t)(off + r + 8) * I_ + n;
                float v2 = c[mt][nt][2], v3 = c[mt][nt][3];
                p[0] = __uint_as_float(f2tf(v2 / (1.f + expf(-v2))));
                p[1] = __uint_as_float(f2tf(v3 / (1.f + expf(-v3))));
            }
        }
    }
}

// ---------------- GEMM2: out[tok] += score * (g_h @ tf32(w2[e])) ----------------
__global__ __launch_bounds__(256, 2) void k_ffn2(const float* __restrict__ w2,
                                                 float* __restrict__ out) {
    const int e    = blockIdx.z;
    const int cnt  = g_cnt[e];
    const int row0 = blockIdx.y * 128;
    if (row0 >= cnt) return;
    const int n0b = blockIdx.x * 128;
    const int off = g_off[e];
    const float* Bw = w2 + (size_t)e * I_ * D_;

    extern __shared__ float dsm[];
    float* Abase = dsm;
    float* Bbase = dsm + STG * A_STAGE_F;

    const int tid = threadIdx.x;

    const int rA  = tid >> 2;
    const int kcA = (tid & 3) * 4;
    const int gr0 = min(row0 + rA,      cnt - 1);
    const int gr1 = min(row0 + rA + 64, cnt - 1);
    const float* aS0 = g_h + (size_t)(off + gr0) * I_ + kcA;
    const float* aS1 = g_h + (size_t)(off + gr1) * I_ + kcA;
    const int rA1 = rA + 64;
    const unsigned aD0 = (unsigned)__cvta_generic_to_shared(
        &Abase[rA  * 16 + ((kcA + 4 * ((rA  >> 1) & 3)) & 15)]);
    const unsigned aD1 = (unsigned)__cvta_generic_to_shared(
        &Abase[rA1 * 16 + ((kcA + 4 * ((rA1 >> 1) & 3)) & 15)]);

    const int rB  = tid >> 5;
    const int ncB = (tid & 31) * 4;
    const float* bS0 = Bw + (size_t)rB * D_ + n0b + ncB;
    const float* bS1 = bS0 + (size_t)8 * D_;
    float* bP0 = &Bbase[rB * 128 + (ncB ^ (8 * (rB & 3)))];
    float* bP1 = &Bbase[(rB + 8) * 128 + (ncB ^ (8 * (rB & 3)))];

    const int wid = tid >> 5, lane = tid & 31;
    const int wm = wid & 3, wn = wid >> 2;
    const int qr = lane >> 2, qc = lane & 3;

    float c[2][8][4];
#pragma unroll
    for (int i = 0; i < 2; i++)
#pragma unroll
        for (int j = 0; j < 8; j++)
#pragma unroll
            for (int l = 0; l < 4; l++) c[i][j][l] = 0.f;

    const int KT = I_ / 16;   // 128
#pragma unroll
    for (int p = 0; p < 4; p++) {
        const unsigned so = p * (A_STAGE_F * 4);
        const int k0 = p * 16;
        cp16(aD0 + so, aS0 + k0);
        cp16(aD1 + so, aS1 + k0);
        cp_commit();
        *(float4*)(bP0 + p * B_STAGE_F) = cvt4(*(const float4*)(bS0 + (size_t)k0 * D_));
        *(float4*)(bP1 + p * B_STAGE_F) = cvt4(*(const float4*)(bS1 + (size_t)k0 * D_));
    }
    float4 nb0 = *(const float4*)(bS0 + (size_t)64 * D_);
    float4 nb1 = *(const float4*)(bS1 + (size_t)64 * D_);

    int scur = 0, spre = 4;
    for (int kt = 0; kt < KT; kt++) {
        if (!(kt & 1)) { cp_wait2(); __syncthreads(); }
        if (kt + 4 < KT) {
            const unsigned so = spre * (A_STAGE_F * 4);
            const int k0 = (kt + 4) * 16;
            cp16(aD0 + so, aS0 + k0);
            cp16(aD1 + so, aS1 + k0);
            *(float4*)(bP0 + spre * B_STAGE_F) = cvt4(nb0);
            *(float4*)(bP1 + spre * B_STAGE_F) = cvt4(nb1);
        }
        cp_commit();
        if (kt + 5 < KT) {
            const int k0 = (kt + 5) * 16;
            nb0 = *(const float4*)(bS0 + (size_t)k0 * D_);
            nb1 = *(const float4*)(bS1 + (size_t)k0 * D_);
        }
        const float* Ab = Abase + scur * A_STAGE_F;
        const float* Bb = Bbase + scur * B_STAGE_F;
#pragma unroll
        for (int ks = 0; ks < 2; ks++) {
            const int kb = ks * 8 + qc;
            unsigned af[2][4];
#pragma unroll
            for (int mt = 0; mt < 2; mt++) {
                const int mlo = wm * 32 + mt * 16 + qr;
                const int mhi = mlo + 8;
                af[mt][0] = __float_as_uint(Ab[mlo * 16 + ((kb     + 4 * ((mlo >> 1) & 3)) & 15)]);
                af[mt][1] = __float_as_uint(Ab[mhi * 16 + ((kb     + 4 * ((mhi >> 1) & 3)) & 15)]);
                af[mt][2] = __float_as_uint(Ab[mlo * 16 + ((kb + 4 + 4 * ((mlo >> 1) & 3)) & 15)]);
                af[mt][3] = __float_as_uint(Ab[mhi * 16 + ((kb + 4 + 4 * ((mhi >> 1) & 3)) & 15)]);
            }
#pragma unroll
            for (int nt = 0; nt < 8; nt++) {
                const int n = wn * 64 + nt * 8 + qr;
                const unsigned sw = n ^ (8 * (kb & 3));
                unsigned bf[2];
                bf[0] = __float_as_uint(Bb[kb * 128 + sw]);
                bf[1] = __float_as_uint(Bb[(kb + 4) * 128 + sw]);
                mma_tf32(c[0][nt], af[0], bf);
                mma_tf32(c[1][nt], af[1], bf);
            }
        }
        if (++scur == STG) scur = 0;
        if (++spre == STG) spre = 0;
    }

    // epilogue: scaled atomic scatter
#pragma unroll
    for (int mt = 0; mt < 2; mt++) {
        const int r = row0 + wm * 32 + mt * 16 + qr;
        int   tok0 = 0, tok1 = 0; float s0 = 0.f, s1 = 0.f;
        const bool v0 = (r < cnt), v1 = (r + 8 < cnt);
        if (v0) { tok0 = g_tok[e * T_ + r];     s0 = g_scr[e * T_ + r]; }
        if (v1) { tok1 = g_tok[e * T_ + r + 8]; s1 = g_scr[e * T_ + r + 8]; }
#pragma unroll
        for (int nt = 0; nt < 8; nt++) {
            const int n = n0b + wn * 64 + nt * 8 + 2 * qc;
            if (v0) {
                float* p = out + (size_t)tok0 * D_ + n;
                atomicAdd(p,     s0 * c[mt][nt][0]);
                atomicAdd(p + 1, s0 * c[mt][nt][1]);
            }
            if (v1) {
                float* p = out + (size_t)tok1 * D_ + n;
                atomicAdd(p,     s1 * c[mt][nt][2]);
                atomicAdd(p + 1, s1 * c[mt][nt][3]);
            }
        }
    }
}

// ---------------- launch ----------------
extern "C" void kernel_launch(void* const* d_in, const int* in_sizes, int n_in,
                              void* d_out, int out_size) {
    const float* x  = (const float*)d_in[0];
    const float* gw = (const float*)d_in[1];
    const float* w1 = (const float*)d_in[2];
    const float* w2 = (const float*)d_in[3];
    float* out = (float*)d_out;

    static bool attr_set = false;
    if (!attr_set) {
        cudaFuncSetAttribute(k_ffn1, cudaFuncAttributeMaxDynamicSharedMemorySize, SMEM_TOT);
        cudaFuncSetAttribute(k_ffn2, cudaFuncAttributeMaxDynamicSharedMemorySize, SMEM_TOT);
        attr_set = true;
    }

    k_init<<<1, 32>>>();
    k_gate<<<T_ / 8, 256>>>(x, gw, out);
    k_prefix<<<1, 32>>>();
    k_ffn1<<<dim3(I_ / 128, T_ / 128, E_), 256, SMEM_TOT>>>(w1);
    k_ffn2<<<dim3(D_ / 128, T_ / 128, E_), 256, SMEM_TOT>>>(w2, out);
}

// round 12
// speedup vs baseline: 1.1321x; 1.0087x over previous
#include <cuda_runtime.h>
#include <math.h>
#include <stdint.h>

#define T_ 2048
#define D_ 1024
#define I_ 2048
#define E_ 8

// ---------------- device scratch ----------------
__device__ int   g_cnt[E_];
__device__ int   g_off[E_];
__device__ int   g_tok[E_ * T_];
__device__ float g_scr[E_ * T_];
__device__ float g_h[(size_t)2 * T_ * I_];        // 4096 x 2048 fp32 (tf32-rounded)
__device__ float x_r[(size_t)T_ * D_];            // tf32-rounded x

// ---------------- helpers ----------------
__device__ __forceinline__ unsigned f2tf(float f) {
    unsigned u; asm("cvt.rna.tf32.f32 %0, %1;" : "=r"(u) : "f"(f)); return u;
}
__device__ __forceinline__ float4 cvt4(float4 v) {
    float4 r;
    r.x = __uint_as_float(f2tf(v.x));
    r.y = __uint_as_float(f2tf(v.y));
    r.z = __uint_as_float(f2tf(v.z));
    r.w = __uint_as_float(f2tf(v.w));
    return r;
}
__device__ __forceinline__ void mma_tf32(float* c, const unsigned* a, const unsigned* b) {
    asm volatile("mma.sync.aligned.m16n8k8.row.col.f32.tf32.tf32.f32 "
                 "{%0,%1,%2,%3}, {%4,%5,%6,%7}, {%8,%9}, {%0,%1,%2,%3};"
                 : "+f"(c[0]), "+f"(c[1]), "+f"(c[2]), "+f"(c[3])
                 : "r"(a[0]), "r"(a[1]), "r"(a[2]), "r"(a[3]), "r"(b[0]), "r"(b[1]));
}
__device__ __forceinline__ void cp16(unsigned dst, const void* src) {
    asm volatile("cp.async.cg.shared.global [%0], [%1], 16;" :: "r"(dst), "l"(src));
}
__device__ __forceinline__ void cp_commit() { asm volatile("cp.async.commit_group;"); }
__device__ __forceinline__ void cp_wait1()  { asm volatile("cp.async.wait_group 1;"); }

// 7-stage pipeline smem: A planes then B planes, 8KB each per stage
#define STG 7
#define A_STAGE_F 2048            // floats per A stage (128x16)
#define B_STAGE_F 2048            // floats per B stage (16x128)
#define SMEM_TOT (STG * (A_STAGE_F + B_STAGE_F) * 4)   // 114688 bytes

// ---------------- init: zero routing counters ----------------
__global__ void k_init() {
    if (threadIdx.x < E_) g_cnt[threadIdx.x] = 0;
}

// ---------------- fused gate: logits + top2 + x_r write + out zero ----------------
__global__ void k_gate(const float* __restrict__ x, const float* __restrict__ gw,
                       float* __restrict__ out) {
    const int t    = blockIdx.x * 8 + (threadIdx.x >> 5);
    const int lane = threadIdx.x & 31;
    const float* xr = x + (size_t)t * D_;
    float*       xo = x_r + (size_t)t * D_;
    float*       oo = out + (size_t)t * D_;
    const float4 z4 = make_float4(0.f, 0.f, 0.f, 0.f);

    float p[E_];
#pragma unroll
    for (int e = 0; e < E_; e++) p[e] = 0.f;

    for (int d = lane * 4; d < D_; d += 128) {
        float4 xv = *(const float4*)(xr + d);
        *(float4*)(xo + d) = cvt4(xv);
        *(float4*)(oo + d) = z4;
#pragma unroll
        for (int e = 0; e < E_; e++) {
            float4 gv = *(const float4*)(gw + e * D_ + d);
            p[e] += xv.x * gv.x + xv.y * gv.y + xv.z * gv.z + xv.w * gv.w;
        }
    }
#pragma unroll
    for (int o = 16; o; o >>= 1) {
#pragma unroll
        for (int e = 0; e < E_; e++) p[e] += __shfl_down_sync(0xffffffffu, p[e], o);
    }

    if (lane == 0) {
        float mx = p[0];
#pragma unroll
        for (int e = 1; e < E_; e++) mx = fmaxf(mx, p[e]);
        float pr[E_]; float den = 0.f;
#pragma unroll
        for (int e = 0; e < E_; e++) { pr[e] = expf(p[e] - mx); den += pr[e]; }
        float inv = 1.f / den;
#pragma unroll
        for (int e = 0; e < E_; e++) pr[e] *= inv;

        int e1 = 0;
#pragma unroll
        for (int e = 1; e < E_; e++) if (pr[e] > pr[e1]) e1 = e;
        int e2 = (e1 == 0) ? 1 : 0;
#pragma unroll
        for (int e = 0; e < E_; e++) if (e != e1 && pr[e] > pr[e2]) e2 = e;

        int i1 = atomicAdd(&g_cnt[e1], 1);
        g_tok[e1 * T_ + i1] = t; g_scr[e1 * T_ + i1] = pr[e1];
        int i2 = atomicAdd(&g_cnt[e2], 1);
        g_tok[e2 * T_ + i2] = t; g_scr[e2 * T_ + i2] = pr[e2];
    }
}

__global__ void k_prefix() {
    if (threadIdx.x == 0) {
        int s = 0;
#pragma unroll
        for (int e = 0; e < E_; e++) { g_off[e] = s; s += g_cnt[e]; }
    }
}

// Swizzles (conflict-free for tf32 m16n8k8 fragment reads):
//   A smem [128][16]: kswz = (k + 4*((m>>1)&3)) & 15
//   B smem [16][128]: nswz = n ^ (8*(k&3))

// ---------------- GEMM1: h = silu(gather(x_r) @ tf32(w1[e])) ----------------
__global__ __launch_bounds__(256, 2) void k_ffn1(const float* __restrict__ w1) {
    const int e    = blockIdx.z;
    const int cnt  = g_cnt[e];
    const int row0 = blockIdx.y * 128;
    if (row0 >= cnt) return;
    const int n0b = blockIdx.x * 128;
    const int off = g_off[e];
    const float* Bw = w1 + (size_t)e * D_ * I_;

    extern __shared__ float dsm[];
    float* Abase = dsm;                          // 7 stages x 2048 f
    float* Bbase = dsm + STG * A_STAGE_F;        // 7 stages x 2048 f

    const int tid = threadIdx.x;

    const int rA  = tid >> 2;            // 0..63
    const int kcA = (tid & 3) * 4;
    const int gr0 = min(row0 + rA,      cnt - 1);
    const int gr1 = min(row0 + rA + 64, cnt - 1);
    const float* aS0 = x_r + (size_t)g_tok[e * T_ + gr0] * D_ + kcA;
    const float* aS1 = x_r + (size_t)g_tok[e * T_ + gr1] * D_ + kcA;
    const int rA1 = rA + 64;
    const unsigned aD0 = (unsigned)__cvta_generic_to_shared(
        &Abase[rA  * 16 + ((kcA + 4 * ((rA  >> 1) & 3)) & 15)]);
    const unsigned aD1 = (unsigned)__cvta_generic_to_shared(
        &Abase[rA1 * 16 + ((kcA + 4 * ((rA1 >> 1) & 3)) & 15)]);

    const int rB  = tid >> 5;            // 0..7
    const int ncB = (tid & 31) * 4;
    const float* bS0 = Bw + (size_t)rB * I_ + n0b + ncB;
    const float* bS1 = bS0 + (size_t)8 * I_;
    float* bP0 = &Bbase[rB * 128 + (ncB ^ (8 * (rB & 3)))];
    float* bP1 = &Bbase[(rB + 8) * 128 + (ncB ^ (8 * (rB & 3)))];

    const int wid = tid >> 5, lane = tid & 31;
    const int wm = wid & 3, wn = wid >> 2;
    const int qr = lane >> 2, qc = lane & 3;

    float c[2][8][4];
#pragma unroll
    for (int i = 0; i < 2; i++)
#pragma unroll
        for (int j = 0; j < 8; j++)
#pragma unroll
            for (int l = 0; l < 4; l++) c[i][j][l] = 0.f;

    const int KT = D_ / 16;   // 64
    // prologue: A tiles 0..3 via cp.async (one commit each); B tiles 0..3 direct
#pragma unroll
    for (int p = 0; p < 4; p++) {
        const unsigned so = p * (A_STAGE_F * 4);
        const int k0 = p * 16;
        cp16(aD0 + so, aS0 + k0);
        cp16(aD1 + so, aS1 + k0);
        cp_commit();
        *(float4*)(bP0 + p * B_STAGE_F) = cvt4(*(const float4*)(bS0 + (size_t)k0 * I_));
        *(float4*)(bP1 + p * B_STAGE_F) = cvt4(*(const float4*)(bS1 + (size_t)k0 * I_));
    }
    float4 nb0 = *(const float4*)(bS0 + (size_t)64 * I_);   // B tile 4
    float4 nb1 = *(const float4*)(bS1 + (size_t)64 * I_);

    int scur = 0, spre = 4, s3 = 0;
    for (int kt = 0; kt < KT; kt++) {
        if (s3 == 0) { cp_wait1(); __syncthreads(); }
        if (kt + 4 < KT) {
            const unsigned so = spre * (A_STAGE_F * 4);
            const int k0 = (kt + 4) * 16;
            cp16(aD0 + so, aS0 + k0);
            cp16(aD1 + so, aS1 + k0);
            *(float4*)(bP0 + spre * B_STAGE_F) = cvt4(nb0);
            *(float4*)(bP1 + spre * B_STAGE_F) = cvt4(nb1);
        }
        cp_commit();
        if (kt + 5 < KT) {
            const int k0 = (kt + 5) * 16;
            nb0 = *(const float4*)(bS0 + (size_t)k0 * I_);
            nb1 = *(const float4*)(bS1 + (size_t)k0 * I_);
        }
        const float* Ab = Abase + scur * A_STAGE_F;
        const float* Bb = Bbase + scur * B_STAGE_F;
#pragma unroll
        for (int ks = 0; ks < 2; ks++) {
            const int kb = ks * 8 + qc;
            unsigned af[2][4];
#pragma unroll
            for (int mt = 0; mt < 2; mt++) {
                const int mlo = wm * 32 + mt * 16 + qr;
                const int mhi = mlo + 8;
                af[mt][0] = __float_as_uint(Ab[mlo * 16 + ((kb     + 4 * ((mlo >> 1) & 3)) & 15)]);
                af[mt][1] = __float_as_uint(Ab[mhi * 16 + ((kb     + 4 * ((mhi >> 1) & 3)) & 15)]);
                af[mt][2] = __float_as_uint(Ab[mlo * 16 + ((kb + 4 + 4 * ((mlo >> 1) & 3)) & 15)]);
                af[mt][3] = __float_as_uint(Ab[mhi * 16 + ((kb + 4 + 4 * ((mhi >> 1) & 3)) & 15)]);
            }
#pragma unroll
            for (int nt = 0; nt < 8; nt++) {
                const int n = wn * 64 + nt * 8 + qr;
                const unsigned sw = n ^ (8 * (kb & 3));
                unsigned bf[2];
                bf[0] = __float_as_uint(Bb[kb * 128 + sw]);
                bf[1] = __float_as_uint(Bb[(kb + 4) * 128 + sw]);
                mma_tf32(c[0][nt], af[0], bf);
                mma_tf32(c[1][nt], af[1], bf);
            }
        }
        if (++scur == STG) scur = 0;
        if (++spre == STG) spre = 0;
        if (++s3 == 3) s3 = 0;
    }

    // epilogue: silu -> g_h (stored tf32-rounded, so ffn2 needs no CVT for A)
#pragma unroll
    for (int mt = 0; mt < 2; mt++) {
        const int r = row0 + wm * 32 + mt * 16 + qr;
#pragma unroll
        for (int nt = 0; nt < 8; nt++) {
            const int n = n0b + wn * 64 + nt * 8 + 2 * qc;
            if (r < cnt) {
                float* p = g_h + (size_t)(off + r) * I_ + n;
                float v0 = c[mt][nt][0], v1 = c[mt][nt][1];
                p[0] = __uint_as_float(f2tf(v0 / (1.f + expf(-v0))));
                p[1] = __uint_as_float(f2tf(v1 / (1.f + expf(-v1))));
            }
            if (r + 8 < cnt) {
                float* p = g_h + (size_t)(off + r + 8) * I_ + n;
                float v2 = c[mt][nt][2], v3 = c[mt][nt][3];
                p[0] = __uint_as_float(f2tf(v2 / (1.f + expf(-v2))));
                p[1] = __uint_as_float(f2tf(v3 / (1.f + expf(-v3))));
            }
        }
    }
}

// ---------------- GEMM2: out[tok] += score * (g_h @ tf32(w2[e])) ----------------
__global__ __launch_bounds__(256, 2) void k_ffn2(const float* __restrict__ w2,
                                                 float* __restrict__ out) {
    const int e    = blockIdx.z;
    const int cnt  = g_cnt[e];
    const int row0 = blockIdx.y * 128;
    if (row0 >= cnt) return;
    const int n0b = blockIdx.x * 128;
    const int off = g_off[e];
    const float* Bw = w2 + (size_t)e * I_ * D_;

    extern __shared__ float dsm[];
    float* Abase = dsm;
    float* Bbase = dsm + STG * A_STAGE_F;

    const int tid = threadIdx.x;

    const int rA  = tid >> 2;
    const int kcA = (tid & 3) * 4;
    const int gr0 = min(row0 + rA,      cnt - 1);
    const int gr1 = min(row0 + rA + 64, cnt - 1);
    const float* aS0 = g_h + (size_t)(off + gr0) * I_ + kcA;
    const float* aS1 = g_h + (size_t)(off + gr1) * I_ + kcA;
    const int rA1 = rA + 64;
    const unsigned aD0 = (unsigned)__cvta_generic_to_shared(
        &Abase[rA  * 16 + ((kcA + 4 * ((rA  >> 1) & 3)) & 15)]);
    const unsigned aD1 = (unsigned)__cvta_generic_to_shared(
        &Abase[rA1 * 16 + ((kcA + 4 * ((rA1 >> 1) & 3)) & 15)]);

    const int rB  = tid >> 5;
    const int ncB = (tid & 31) * 4;
    const float* bS0 = Bw + (size_t)rB * D_ + n0b + ncB;
    const float* bS1 = bS0 + (size_t)8 * D_;
    float* bP0 = &Bbase[rB * 128 + (ncB ^ (8 * (rB & 3)))];
    float* bP1 = &Bbase[(rB + 8) * 128 + (ncB ^ (8 * (rB & 3)))];

    const int wid = tid >> 5, lane = tid & 31;
    const int wm = wid & 3, wn = wid >> 2;
    const int qr = lane >> 2, qc = lane & 3;

    float c[2][8][4];
#pragma unroll
    for (int i = 0; i < 2; i++)
#pragma unroll
        for (int j = 0; j < 8; j++)
#pragma unroll
            for (int l = 0; l < 4; l++) c[i][j][l] = 0.f;

    const int KT = I_ / 16;   // 128
#pragma unroll
    for (int p = 0; p < 4; p++) {
        const unsigned so = p * (A_STAGE_F * 4);
        const int k0 = p * 16;
        cp16(aD0 + so, aS0 + k0);
        cp16(aD1 + so, aS1 + k0);
        cp_commit();
        *(float4*)(bP0 + p * B_STAGE_F) = cvt4(*(const float4*)(bS0 + (size_t)k0 * D_));
        *(float4*)(bP1 + p * B_STAGE_F) = cvt4(*(const float4*)(bS1 + (size_t)k0 * D_));
    }
    float4 nb0 = *(const float4*)(bS0 + (size_t)64 * D_);
    float4 nb1 = *(const float4*)(bS1 + (size_t)64 * D_);

    int scur = 0, spre = 4, s3 = 0;
    for (int kt = 0; kt < KT; kt++) {
        if (s3 == 0) { cp_wait1(); __syncthreads(); }
        if (kt + 4 < KT) {
            const unsigned so = spre * (A_STAGE_F * 4);
            const int k0 = (kt + 4) * 16;
            cp16(aD0 + so, aS0 + k0);
            cp16(aD1 + so, aS1 + k0);
            *(float4*)(bP0 + spre * B_STAGE_F) = cvt4(nb0);
            *(float4*)(bP1 + spre * B_STAGE_F) = cvt4(nb1);
        }
        cp_commit();
        if (kt + 5 < KT) {
            const int k0 = (kt + 5) * 16;
            nb0 = *(const float4*)(bS0 + (size_t)k0 * D_);
            nb1 = *(const float4*)(bS1 + (size_t)k0 * D_);
        }
        const float* Ab = Abase + scur * A_STAGE_F;
        const float* Bb = Bbase + scur * B_STAGE_F;
#pragma unroll
        for (int ks = 0; ks < 2; ks++) {
            const int kb = ks * 8 + qc;
            unsigned af[2][4];
#pragma unroll
            for (int mt = 0; mt < 2; mt++) {
                const int mlo = wm * 32 + mt * 16 + qr;
                const int mhi = mlo + 8;
                af[mt][0] = __float_as_uint(Ab[mlo * 16 + ((kb     + 4 * ((mlo >> 1) & 3)) & 15)]);
                af[mt][1] = __float_as_uint(Ab[mhi * 16 + ((kb     + 4 * ((mhi >> 1) & 3)) & 15)]);
                af[mt][2] = __float_as_uint(Ab[mlo * 16 + ((kb + 4 + 4 * ((mlo >> 1) & 3)) & 15)]);
                af[mt][3] = __float_as_uint(Ab[mhi * 16 + ((kb + 4 + 4 * ((mhi >> 1) & 3)) & 15)]);
            }
#pragma unroll
            for (int nt = 0; nt < 8; nt++) {
                const int n = wn * 64 + nt * 8 + qr;
                const unsigned sw = n ^ (8 * (kb & 3));
                unsigned bf[2];
                bf[0] = __float_as_uint(Bb[kb * 128 + sw]);
                bf[1] = __float_as_uint(Bb[(kb + 4) * 128 + sw]);
                mma_tf32(c[0][nt], af[0], bf);
                mma_tf32(c[1][nt], af[1], bf);
            }
        }
        if (++scur == STG) scur = 0;
        if (++spre == STG) spre = 0;
        if (++s3 == 3) s3 = 0;
    }

    // epilogue: scaled atomic scatter
#pragma unroll
    for (int mt = 0; mt < 2; mt++) {
        const int r = row0 + wm * 32 + mt * 16 + qr;
        int   tok0 = 0, tok1 = 0; float s0 = 0.f, s1 = 0.f;
        const bool v0 = (r < cnt), v1 = (r + 8 < cnt);
        if (v0) { tok0 = g_tok[e * T_ + r];     s0 = g_scr[e * T_ + r]; }
        if (v1) { tok1 = g_tok[e * T_ + r + 8]; s1 = g_scr[e * T_ + r + 8]; }
#pragma unroll
        for (int nt = 0; nt < 8; nt++) {
            const int n = n0b + wn * 64 + nt * 8 + 2 * qc;
            if (v0) {
                float* p = out + (size_t)tok0 * D_ + n;
                atomicAdd(p,     s0 * c[mt][nt][0]);
                atomicAdd(p + 1, s0 * c[mt][nt][1]);
            }
            if (v1) {
                float* p = out + (size_t)tok1 * D_ + n;
                atomicAdd(p,     s1 * c[mt][nt][2]);
                atomicAdd(p + 1, s1 * c[mt][nt][3]);
            }
        }
    }
}

// ---------------- launch ----------------
extern "C" void kernel_launch(void* const* d_in, const int* in_sizes, int n_in,
                              void* d_out, int out_size) {
    const float* x  = (const float*)d_in[0];
    const float* gw = (const float*)d_in[1];
    const float* w1 = (const float*)d_in[2];
    const float* w2 = (const float*)d_in[3];
    float* out = (float*)d_out;

    static bool attr_set = false;
    if (!attr_set) {
        cudaFuncSetAttribute(k_ffn1, cudaFuncAttributeMaxDynamicSharedMemorySize, SMEM_TOT);
        cudaFuncSetAttribute(k_ffn2, cudaFuncAttributeMaxDynamicSharedMemorySize, SMEM_TOT);
        attr_set = true;
    }

    k_init<<<1, 32>>>();
    k_gate<<<T_ / 8, 256>>>(x, gw, out);
    k_prefix<<<1, 32>>>();
    k_ffn1<<<dim3(I_ / 128, T_ / 128, E_), 256, SMEM_TOT>>>(w1);
    k_ffn2<<<dim3(D_ / 128, T_ / 128, E_), 256, SMEM_TOT>>>(w2, out);
}

// round 13
// speedup vs baseline: 1.3088x; 1.1560x over previous
#include <cuda_runtime.h>
#include <cuda_fp16.h>
#include <math.h>
#include <stdint.h>

#define T_ 2048
#define D_ 1024
#define I_ 2048
#define E_ 8

// ---------------- device scratch ----------------
__device__ int    g_cnt[E_];
__device__ int    g_off[E_];
__device__ int    g_tok[E_ * T_];
__device__ float  g_scr[E_ * T_];
__device__ __half g_h[(size_t)2 * T_ * I_];     // 4096 x 2048 fp16
__device__ __half x_h[(size_t)T_ * D_];         // fp16 x

// ---------------- helpers ----------------
__device__ __forceinline__ unsigned pack2(float lo, float hi) {
    __half2 h = __floats2half2_rn(lo, hi);
    return *(unsigned*)&h;
}
__device__ __forceinline__ void mma_f16(float* c, const unsigned* a, const unsigned* b) {
    asm volatile("mma.sync.aligned.m16n8k16.row.col.f32.f16.f16.f32 "
                 "{%0,%1,%2,%3}, {%4,%5,%6,%7}, {%8,%9}, {%0,%1,%2,%3};"
                 : "+f"(c[0]), "+f"(c[1]), "+f"(c[2]), "+f"(c[3])
                 : "r"(a[0]), "r"(a[1]), "r"(a[2]), "r"(a[3]), "r"(b[0]), "r"(b[1]));
}
__device__ __forceinline__ void cp16(unsigned dst, const void* src) {
    asm volatile("cp.async.cg.shared.global [%0], [%1], 16;" :: "r"(dst), "l"(src));
}
__device__ __forceinline__ void cp_commit() { asm volatile("cp.async.commit_group;"); }
__device__ __forceinline__ void cp_wait1()  { asm volatile("cp.async.wait_group 1;"); }

// 7-stage pipeline; per stage: A = 128 rows x 8 k-pair u32 (4KB), B = 8 kp x 128 n u32 (4KB)
#define STG 7
#define A_ST 1024                  // uint32 per A stage
#define B_ST 1024                  // uint32 per B stage
#define SMEM_TOT (STG * (A_ST + B_ST) * 4)   // 57344 bytes

// ---------------- init: zero routing counters ----------------
__global__ void k_init() {
    if (threadIdx.x < E_) g_cnt[threadIdx.x] = 0;
}

// ---------------- fused gate: logits + top2 + x_h write + out zero ----------------
__global__ void k_gate(const float* __restrict__ x, const float* __restrict__ gw,
                       float* __restrict__ out) {
    const int t    = blockIdx.x * 8 + (threadIdx.x >> 5);
    const int lane = threadIdx.x & 31;
    const float* xr = x + (size_t)t * D_;
    __half*      xo = x_h + (size_t)t * D_;
    float*       oo = out + (size_t)t * D_;
    const float4 z4 = make_float4(0.f, 0.f, 0.f, 0.f);

    float p[E_];
#pragma unroll
    for (int e = 0; e < E_; e++) p[e] = 0.f;

    for (int d = lane * 4; d < D_; d += 128) {
        float4 xv = *(const float4*)(xr + d);
        uint2 hv;
        hv.x = pack2(xv.x, xv.y);
        hv.y = pack2(xv.z, xv.w);
        *(uint2*)(xo + d) = hv;            // fused fp16 conversion of x
        *(float4*)(oo + d) = z4;           // fused output zeroing
#pragma unroll
        for (int e = 0; e < E_; e++) {
            float4 gv = *(const float4*)(gw + e * D_ + d);
            p[e] += xv.x * gv.x + xv.y * gv.y + xv.z * gv.z + xv.w * gv.w;
        }
    }
#pragma unroll
    for (int o = 16; o; o >>= 1) {
#pragma unroll
        for (int e = 0; e < E_; e++) p[e] += __shfl_down_sync(0xffffffffu, p[e], o);
    }

    if (lane == 0) {
        float mx = p[0];
#pragma unroll
        for (int e = 1; e < E_; e++) mx = fmaxf(mx, p[e]);
        float pr[E_]; float den = 0.f;
#pragma unroll
        for (int e = 0; e < E_; e++) { pr[e] = expf(p[e] - mx); den += pr[e]; }
        float inv = 1.f / den;
#pragma unroll
        for (int e = 0; e < E_; e++) pr[e] *= inv;

        int e1 = 0;
#pragma unroll
        for (int e = 1; e < E_; e++) if (pr[e] > pr[e1]) e1 = e;
        int e2 = (e1 == 0) ? 1 : 0;
#pragma unroll
        for (int e = 0; e < E_; e++) if (e != e1 && pr[e] > pr[e2]) e2 = e;

        int i1 = atomicAdd(&g_cnt[e1], 1);
        g_tok[e1 * T_ + i1] = t; g_scr[e1 * T_ + i1] = pr[e1];
        int i2 = atomicAdd(&g_cnt[e2], 1);
        g_tok[e2 * T_ + i2] = t; g_scr[e2 * T_ + i2] = pr[e2];
    }
}

__global__ void k_prefix() {
    if (threadIdx.x == 0) {
        int s = 0;
#pragma unroll
        for (int e = 0; e < E_; e++) { g_off[e] = s; s += g_cnt[e]; }
    }
}

// Layouts (conflict-audited):
//   A smem: [128 m][8 kp] u32 (kp = k/2 pair), swizzled col' = kp ^ (4*((m>>2)&1))
//   B smem: [8 kp][128 n] u32, swizzled col' = n ^ ((kp&3)<<3)

// ---------------- GEMM1: h = silu(gather(x_h) @ fp16(w1[e])) ----------------
__global__ __launch_bounds__(256, 2) void k_ffn1(const float* __restrict__ w1) {
    const int e    = blockIdx.z;
    const int cnt  = g_cnt[e];
    const int row0 = blockIdx.y * 128;
    if (row0 >= cnt) return;
    const int n0b = blockIdx.x * 128;
    const int off = g_off[e];
    const float* Bw = w1 + (size_t)e * D_ * I_;

    extern __shared__ unsigned dsm4[];
    unsigned* Abase = dsm4;                   // 7 stages x 1024 u32
    unsigned* Bbase = dsm4 + STG * A_ST;      // 7 stages x 1024 u32

    const int tid = threadIdx.x;

    // A staging: thread -> (row = tid>>1, half = tid&1), 16B cp.async
    const int rA   = tid >> 1;             // 0..127
    const int half = tid & 1;
    const int gr   = min(row0 + rA, cnt - 1);
    const __half* aS = x_h + (size_t)g_tok[e * T_ + gr] * D_ + half * 8;
    const unsigned aD = (unsigned)__cvta_generic_to_shared(
        &Abase[rA * 8 + 4 * (half ^ ((rA >> 2) & 1))]);

    // B staging: warp = kp (0..7), lane -> n0 = lane*4; transpose-pack 2 float4 -> uint4
    const int kp  = tid >> 5;
    const int n0B = (tid & 31) * 4;
    const float* bS0 = Bw + (size_t)(2 * kp) * I_ + n0b + n0B;
    const float* bS1 = bS0 + I_;
    unsigned* bP = &Bbase[kp * 128 + (n0B ^ ((kp & 3) << 3))];

    const int wid = tid >> 5, lane = tid & 31;
    const int wm = wid & 3, wn = wid >> 2;
    const int qr = lane >> 2, qc = lane & 3;
    const int sA = 4 * ((qr >> 2) & 1);

    float c[2][8][4];
#pragma unroll
    for (int i = 0; i < 2; i++)
#pragma unroll
        for (int j = 0; j < 8; j++)
#pragma unroll
            for (int l = 0; l < 4; l++) c[i][j][l] = 0.f;

    const int KT = D_ / 16;   // 64
    // prologue: A tiles 0..3 cp.async; B tiles 0..3 LDG->pack->STS; B tile 4 to regs
#pragma unroll
    for (int p = 0; p < 4; p++) {
        const int k0 = p * 16;
        cp16(aD + p * (A_ST * 4), aS + k0);
        cp_commit();
        float4 f0 = *(const float4*)(bS0 + (size_t)k0 * I_);
        float4 f1 = *(const float4*)(bS1 + (size_t)k0 * I_);
        *(uint4*)(bP + p * B_ST) = make_uint4(pack2(f0.x, f1.x), pack2(f0.y, f1.y),
                                              pack2(f0.z, f1.z), pack2(f0.w, f1.w));
    }
    float4 nb0 = *(const float4*)(bS0 + (size_t)64 * I_);
    float4 nb1 = *(const float4*)(bS1 + (size_t)64 * I_);

    int scur = 0, spre = 4, s3 = 0;
    for (int kt = 0; kt < KT; kt++) {
        if (s3 == 0) { cp_wait1(); __syncthreads(); }
        if (kt + 4 < KT) {
            cp16(aD + spre * (A_ST * 4), aS + (kt + 4) * 16);
            *(uint4*)(bP + spre * B_ST) = make_uint4(pack2(nb0.x, nb1.x), pack2(nb0.y, nb1.y),
                                                     pack2(nb0.z, nb1.z), pack2(nb0.w, nb1.w));
        }
        cp_commit();
        if (kt + 5 < KT) {
            const int k0 = (kt + 5) * 16;
            nb0 = *(const float4*)(bS0 + (size_t)k0 * I_);
            nb1 = *(const float4*)(bS1 + (size_t)k0 * I_);
        }
        const unsigned* Ab = Abase + scur * A_ST;
        const unsigned* Bb = Bbase + scur * B_ST;

        unsigned af[2][4];
#pragma unroll
        for (int mt = 0; mt < 2; mt++) {
            const int mlo = wm * 32 + mt * 16 + qr;
            const int mhi = mlo + 8;
            af[mt][0] = Ab[mlo * 8 + (qc ^ sA)];
            af[mt][1] = Ab[mhi * 8 + (qc ^ sA)];
            af[mt][2] = Ab[mlo * 8 + ((qc + 4) ^ sA)];
            af[mt][3] = Ab[mhi * 8 + ((qc + 4) ^ sA)];
        }
#pragma unroll
        for (int nt = 0; nt < 8; nt++) {
            const int n = wn * 64 + nt * 8 + qr;
            const int sw = n ^ (qc << 3);
            unsigned bf[2];
            bf[0] = Bb[qc * 128 + sw];
            bf[1] = Bb[(qc + 4) * 128 + sw];
            mma_f16(c[0][nt], af[0], bf);
            mma_f16(c[1][nt], af[1], bf);
        }
        if (++scur == STG) scur = 0;
        if (++spre == STG) spre = 0;
        if (++s3 == 3) s3 = 0;
    }

    // epilogue: silu -> g_h (fp16 pairs)
#pragma unroll
    for (int mt = 0; mt < 2; mt++) {
        const int r = row0 + wm * 32 + mt * 16 + qr;
#pragma unroll
        for (int nt = 0; nt < 8; nt++) {
            const int n = n0b + wn * 64 + nt * 8 + 2 * qc;
            if (r < cnt) {
                float v0 = c[mt][nt][0], v1 = c[mt][nt][1];
                v0 = v0 / (1.f + expf(-v0));
                v1 = v1 / (1.f + expf(-v1));
                *(unsigned*)&g_h[(size_t)(off + r) * I_ + n] = pack2(v0, v1);
            }
            if (r + 8 < cnt) {
                float v2 = c[mt][nt][2], v3 = c[mt][nt][3];
                v2 = v2 / (1.f + expf(-v2));
                v3 = v3 / (1.f + expf(-v3));
                *(unsigned*)&g_h[(size_t)(off + r + 8) * I_ + n] = pack2(v2, v3);
            }
        }
    }
}

// ---------------- GEMM2: out[tok] += score * (g_h @ fp16(w2[e])) ----------------
__global__ __launch_bounds__(256, 2) void k_ffn2(const float* __restrict__ w2,
                                                 float* __restrict__ out) {
    const int e    = blockIdx.z;
    const int cnt  = g_cnt[e];
    const int row0 = blockIdx.y * 128;
    if (row0 >= cnt) return;
    const int n0b = blockIdx.x * 128;
    const int off = g_off[e];
    const float* Bw = w2 + (size_t)e * I_ * D_;

    extern __shared__ unsigned dsm4[];
    unsigned* Abase = dsm4;
    unsigned* Bbase = dsm4 + STG * A_ST;

    const int tid = threadIdx.x;

    const int rA   = tid >> 1;
    const int half = tid & 1;
    const int gr   = min(row0 + rA, cnt - 1);
    const __half* aS = g_h + (size_t)(off + gr) * I_ + half * 8;
    const unsigned aD = (unsigned)__cvta_generic_to_shared(
        &Abase[rA * 8 + 4 * (half ^ ((rA >> 2) & 1))]);

    const int kp  = tid >> 5;
    const int n0B = (tid & 31) * 4;
    const float* bS0 = Bw + (size_t)(2 * kp) * D_ + n0b + n0B;
    const float* bS1 = bS0 + D_;
    unsigned* bP = &Bbase[kp * 128 + (n0B ^ ((kp & 3) << 3))];

    const int wid = tid >> 5, lane = tid & 31;
    const int wm = wid & 3, wn = wid >> 2;
    const int qr = lane >> 2, qc = lane & 3;
    const int sA = 4 * ((qr >> 2) & 1);

    float c[2][8][4];
#pragma unroll
    for (int i = 0; i < 2; i++)
#pragma unroll
        for (int j = 0; j < 8; j++)
#pragma unroll
            for (int l = 0; l < 4; l++) c[i][j][l] = 0.f;

    const int KT = I_ / 16;   // 128
#pragma unroll
    for (int p = 0; p < 4; p++) {
        const int k0 = p * 16;
        cp16(aD + p * (A_ST * 4), aS + k0);
        cp_commit();
        float4 f0 = *(const float4*)(bS0 + (size_t)k0 * D_);
        float4 f1 = *(const float4*)(bS1 + (size_t)k0 * D_);
        *(uint4*)(bP + p * B_ST) = make_uint4(pack2(f0.x, f1.x), pack2(f0.y, f1.y),
                                              pack2(f0.z, f1.z), pack2(f0.w, f1.w));
    }
    float4 nb0 = *(const float4*)(bS0 + (size_t)64 * D_);
    float4 nb1 = *(const float4*)(bS1 + (size_t)64 * D_);

    int scur = 0, spre = 4, s3 = 0;
    for (int kt = 0; kt < KT; kt++) {
        if (s3 == 0) { cp_wait1(); __syncthreads(); }
        if (kt + 4 < KT) {
            cp16(aD + spre * (A_ST * 4), aS + (kt + 4) * 16);
            *(uint4*)(bP + spre * B_ST) = make_uint4(pack2(nb0.x, nb1.x), pack2(nb0.y, nb1.y),
                                                     pack2(nb0.z, nb1.z), pack2(nb0.w, nb1.w));
        }
        cp_commit();
        if (kt + 5 < KT) {
            const int k0 = (kt + 5) * 16;
            nb0 = *(const float4*)(bS0 + (size_t)k0 * D_);
            nb1 = *(const float4*)(bS1 + (size_t)k0 * D_);
        }
        const unsigned* Ab = Abase + scur * A_ST;
        const unsigned* Bb = Bbase + scur * B_ST;

        unsigned af[2][4];
#pragma unroll
        for (int mt = 0; mt < 2; mt++) {
            const int mlo = wm * 32 + mt * 16 + qr;
            const int mhi = mlo + 8;
            af[mt][0] = Ab[mlo * 8 + (qc ^ sA)];
            af[mt][1] = Ab[mhi * 8 + (qc ^ sA)];
            af[mt][2] = Ab[mlo * 8 + ((qc + 4) ^ sA)];
            af[mt][3] = Ab[mhi * 8 + ((qc + 4) ^ sA)];
        }
#pragma unroll
        for (int nt = 0; nt < 8; nt++) {
            const int n = wn * 64 + nt * 8 + qr;
            const int sw = n ^ (qc << 3);
            unsigned bf[2];
            bf[0] = Bb[qc * 128 + sw];
            bf[1] = Bb[(qc + 4) * 128 + sw];
            mma_f16(c[0][nt], af[0], bf);
            mma_f16(c[1][nt], af[1], bf);
        }
        if (++scur == STG) scur = 0;
        if (++spre == STG) spre = 0;
        if (++s3 == 3) s3 = 0;
    }

    // epilogue: scaled atomic scatter
#pragma unroll
    for (int mt = 0; mt < 2; mt++) {
        const int r = row0 + wm * 32 + mt * 16 + qr;
        int   tok0 = 0, tok1 = 0; float s0 = 0.f, s1 = 0.f;
        const bool v0 = (r < cnt), v1 = (r + 8 < cnt);
        if (v0) { tok0 = g_tok[e * T_ + r];     s0 = g_scr[e * T_ + r]; }
        if (v1) { tok1 = g_tok[e * T_ + r + 8]; s1 = g_scr[e * T_ + r + 8]; }
#pragma unroll
        for (int nt = 0; nt < 8; nt++) {
            const int n = n0b + wn * 64 + nt * 8 + 2 * qc;
            if (v0) {
                float* p = out + (size_t)tok0 * D_ + n;
                atomicAdd(p,     s0 * c[mt][nt][0]);
                atomicAdd(p + 1, s0 * c[mt][nt][1]);
            }
            if (v1) {
                float* p = out + (size_t)tok1 * D_ + n;
                atomicAdd(p,     s1 * c[mt][nt][2]);
                atomicAdd(p + 1, s1 * c[mt][nt][3]);
            }
        }
    }
}

// ---------------- launch ----------------
extern "C" void kernel_launch(void* const* d_in, const int* in_sizes, int n_in,
                              void* d_out, int out_size) {
    const float* x  = (const float*)d_in[0];
    const float* gw = (const float*)d_in[1];
    const float* w1 = (const float*)d_in[2];
    const float* w2 = (const float*)d_in[3];
    float* out = (float*)d_out;

    static bool attr_set = false;
    if (!attr_set) {
        cudaFuncSetAttribute(k_ffn1, cudaFuncAttributeMaxDynamicSharedMemorySize, SMEM_TOT);
        cudaFuncSetAttribute(k_ffn2, cudaFuncAttributeMaxDynamicSharedMemorySize, SMEM_TOT);
        attr_set = true;
    }

    k_init<<<1, 32>>>();
    k_gate<<<T_ / 8, 256>>>(x, gw, out);
    k_prefix<<<1, 32>>>();
    k_ffn1<<<dim3(I_ / 128, T_ / 128, E_), 256, SMEM_TOT>>>(w1);
    k_ffn2<<<dim3(D_ / 128, T_ / 128, E_), 256, SMEM_TOT>>>(w2, out);
}